// round 2
// baseline (speedup 1.0000x reference)
#include <cuda_runtime.h>
#include <cuda_fp16.h>
#include <cstdint>

// ============================================================================
// out[8192,4096] = x[8192,4096] @ W[4096(k),4096(n)] + b
// sm_103 base-ISA path: cp.async multistage + ldmatrix + mma.sync.m16n8k16
// (tcgen05 does not assemble at the harness's compute_103 virtual arch)
// ============================================================================

static constexpr int BATCH = 8192;
static constexpr int IN_F  = 4096;   // K
static constexpr int OUT_F = 4096;   // N

static constexpr int TM = 128;             // CTA tile M
static constexpr int TN = 256;             // CTA tile N
static constexpr int KS = 64;              // K halves per stage (128B per row)
static constexpr int NK = IN_F / KS;       // 64
static constexpr int STAGES = 4;

static constexpr uint32_t A_ST = TM * 128u;                 // 16 KB
static constexpr uint32_t B_ST = TN * 128u;                 // 32 KB
static constexpr uint32_t STAGE = A_ST + B_ST;              // 48 KB
static constexpr uint32_t SMEM_BYTES = 1024u + STAGES * STAGE;  // 197632

// fp16 scratch (device globals = sanctioned scratch)
__device__ __align__(128) __half g_xh[(size_t)BATCH * IN_F];  // x fp16, [M,K] row-major
__device__ __align__(128) __half g_wt[(size_t)OUT_F * IN_F];  // W^T fp16, [N,K] row-major

// ----------------------------------------------------------------------------
__device__ __forceinline__ uint32_t smem_u32(const void* p) {
    uint32_t a;
    asm("{ .reg .u64 t; cvta.to.shared.u64 t, %1; cvt.u32.u64 %0, t; }" : "=r"(a) : "l"(p));
    return a;
}
__device__ __forceinline__ uint32_t sw128(uint32_t off) {
    return off ^ ((off >> 3) & 0x70u);
}
__device__ __forceinline__ void cp16(uint32_t s, const void* g) {
    asm volatile("cp.async.cg.shared.global [%0], [%1], 16;" :: "r"(s), "l"(g));
}
__device__ __forceinline__ void ldsm4(uint32_t& r0, uint32_t& r1, uint32_t& r2, uint32_t& r3,
                                      uint32_t addr) {
    asm volatile("ldmatrix.sync.aligned.m8n8.x4.shared.b16 {%0,%1,%2,%3}, [%4];"
                 : "=r"(r0), "=r"(r1), "=r"(r2), "=r"(r3) : "r"(addr));
}
__device__ __forceinline__ void mma16816(float& c0, float& c1, float& c2, float& c3,
                                         uint32_t a0, uint32_t a1, uint32_t a2, uint32_t a3,
                                         uint32_t b0, uint32_t b1) {
    asm volatile(
        "mma.sync.aligned.m16n8k16.row.col.f32.f16.f16.f32 "
        "{%0,%1,%2,%3}, {%4,%5,%6,%7}, {%8,%9}, {%0,%1,%2,%3};"
        : "+f"(c0), "+f"(c1), "+f"(c2), "+f"(c3)
        : "r"(a0), "r"(a1), "r"(a2), "r"(a3), "r"(b0), "r"(b1));
}

// ----------------------------------------------------------------------------
// Preprocessing
// ----------------------------------------------------------------------------
__global__ void cvt_x_kernel(const float* __restrict__ x) {
    const size_t n8 = (size_t)BATCH * IN_F / 8;
    size_t stride = (size_t)gridDim.x * blockDim.x;
    for (size_t i = (size_t)blockIdx.x * blockDim.x + threadIdx.x; i < n8; i += stride) {
        float4 a = ((const float4*)x)[2 * i];
        float4 c = ((const float4*)x)[2 * i + 1];
        __half2 h0 = __floats2half2_rn(a.x, a.y);
        __half2 h1 = __floats2half2_rn(a.z, a.w);
        __half2 h2 = __floats2half2_rn(c.x, c.y);
        __half2 h3 = __floats2half2_rn(c.z, c.w);
        uint4 o;
        o.x = *reinterpret_cast<uint32_t*>(&h0);
        o.y = *reinterpret_cast<uint32_t*>(&h1);
        o.z = *reinterpret_cast<uint32_t*>(&h2);
        o.w = *reinterpret_cast<uint32_t*>(&h3);
        ((uint4*)g_xh)[i] = o;
    }
}

// einsum 'bi,io->bo': W indexed [i(=k)][o(=n)], row stride OUT_F. Build Wt[n][k].
__global__ void cvt_w_kernel(const float* __restrict__ w) {
    __shared__ __half tile[32][33];
    int i0 = blockIdx.y * 32;
    int o0 = blockIdx.x * 32;
    int tx = threadIdx.x, ty = threadIdx.y;
    #pragma unroll
    for (int k = 0; k < 4; k++) {
        int i = i0 + ty + k * 8;
        tile[ty + k * 8][tx] = __float2half(w[(size_t)i * OUT_F + o0 + tx]);
    }
    __syncthreads();
    #pragma unroll
    for (int k = 0; k < 4; k++) {
        int o = o0 + ty + k * 8;
        g_wt[(size_t)o * IN_F + i0 + tx] = tile[tx][ty + k * 8];
    }
}

// ----------------------------------------------------------------------------
// GEMM: 128x256 tile / CTA, 256 threads (8 warps, 2M x 4N, warp tile 64x64)
// ----------------------------------------------------------------------------
__device__ __forceinline__ void load_stage(uint32_t st, int tid,
                                           const __half* gA, const __half* gB, int kslab) {
    const __half* a = gA + (size_t)kslab * KS;
    const __half* b = gB + (size_t)kslab * KS;
    #pragma unroll
    for (int r = 0; r < 4; r++) {              // A: 1024 chunks / 256 thr
        int id = tid + (r << 8);
        int row = id >> 3;
        int c = id & 7;
        uint32_t sw = sw128(((uint32_t)row << 7) | ((uint32_t)c << 4));
        cp16(st + sw, a + (size_t)row * IN_F + (c << 3));
    }
    #pragma unroll
    for (int r = 0; r < 8; r++) {              // B: 2048 chunks / 256 thr
        int id = tid + (r << 8);
        int row = id >> 3;
        int c = id & 7;
        uint32_t sw = sw128(((uint32_t)row << 7) | ((uint32_t)c << 4));
        cp16(st + A_ST + sw, b + (size_t)row * IN_F + (c << 3));
    }
}

__global__ void __launch_bounds__(256, 1)
gemm_hmma_kernel(const float* __restrict__ bias, float* __restrict__ out) {
    extern __shared__ char smem_raw[];
    const uint32_t S0 = (smem_u32(smem_raw) + 1023u) & ~1023u;

    const int tid  = threadIdx.x;
    const int wid  = tid >> 5;
    const int lane = tid & 31;
    const int wm   = wid & 1;          // 0..1
    const int wn   = wid >> 1;         // 0..3
    const int tile_m = blockIdx.x >> 4;    // 64 m-tiles
    const int tile_n = blockIdx.x & 15;    // 16 n-tiles

    const __half* gA = g_xh + (size_t)tile_m * TM * IN_F;
    const __half* gB = g_wt + (size_t)tile_n * TN * IN_F;

    // Per-lane ldmatrix base offsets (within stage tile)
    // A: row = wm*64 + t*16 + (lane&15); colbyte = kk*32 + (lane>>4)*16
    const uint32_t a_row  = (uint32_t)(wm * 64 + (lane & 15));
    const uint32_t a_colb = (uint32_t)((lane >> 4) << 4);
    // B: row = wn*64 + p*16 + ((lane>>4)<<3) + (lane&7); colbyte = kk*32 + ((lane>>3)&1)*16
    const uint32_t b_row  = (uint32_t)(wn * 64 + ((lane >> 4) << 3) + (lane & 7));
    const uint32_t b_colb = (uint32_t)(((lane >> 3) & 1) << 4);

    float acc[4][8][4];
    #pragma unroll
    for (int t = 0; t < 4; t++)
        #pragma unroll
        for (int j = 0; j < 8; j++)
            #pragma unroll
            for (int q = 0; q < 4; q++) acc[t][j][q] = 0.0f;

    // Prologue
    #pragma unroll
    for (int p = 0; p < STAGES - 1; p++) {
        load_stage(S0 + (uint32_t)p * STAGE, tid, gA, gB, p);
        asm volatile("cp.async.commit_group;" ::: "memory");
    }

    for (int it = 0; it < NK; ++it) {
        asm volatile("cp.async.wait_group %0;" :: "n"(STAGES - 2) : "memory");
        __syncthreads();

        // issue next stage's loads first (overlap with compute)
        const int j = it + (STAGES - 1);
        if (j < NK) {
            load_stage(S0 + (uint32_t)(j % STAGES) * STAGE, tid, gA, gB, j);
        }
        asm volatile("cp.async.commit_group;" ::: "memory");

        const uint32_t stA = S0 + (uint32_t)(it % STAGES) * STAGE;
        const uint32_t stB = stA + A_ST;

        #pragma unroll
        for (int kk = 0; kk < 4; kk++) {
            uint32_t af[4][4], bf[4][4];
            #pragma unroll
            for (int t = 0; t < 4; t++) {
                uint32_t off = (a_row + t * 16u) * 128u + (uint32_t)(kk * 32) + a_colb;
                ldsm4(af[t][0], af[t][1], af[t][2], af[t][3], stA + sw128(off));
            }
            #pragma unroll
            for (int p = 0; p < 4; p++) {
                uint32_t off = (b_row + p * 16u) * 128u + (uint32_t)(kk * 32) + b_colb;
                ldsm4(bf[p][0], bf[p][1], bf[p][2], bf[p][3], stB + sw128(off));
            }
            #pragma unroll
            for (int t = 0; t < 4; t++) {
                #pragma unroll
                for (int p = 0; p < 4; p++) {
                    mma16816(acc[t][2*p][0], acc[t][2*p][1], acc[t][2*p][2], acc[t][2*p][3],
                             af[t][0], af[t][1], af[t][2], af[t][3],
                             bf[p][0], bf[p][1]);
                    mma16816(acc[t][2*p+1][0], acc[t][2*p+1][1], acc[t][2*p+1][2], acc[t][2*p+1][3],
                             af[t][0], af[t][1], af[t][2], af[t][3],
                             bf[p][2], bf[p][3]);
                }
            }
        }
        __syncthreads();
    }

    // Epilogue: acc + bias -> gmem fp32
    const int n_base = tile_n * TN + wn * 64 + (lane & 3) * 2;
    float2 bv[8];
    #pragma unroll
    for (int jj = 0; jj < 8; jj++)
        bv[jj] = *(const float2*)(bias + n_base + jj * 8);

    const int m_base = tile_m * TM + wm * 64 + (lane >> 2);
    #pragma unroll
    for (int t = 0; t < 4; t++) {
        float* r0 = out + (size_t)(m_base + t * 16) * OUT_F + n_base;
        float* r1 = r0 + 8 * OUT_F;
        #pragma unroll
        for (int jj = 0; jj < 8; jj++) {
            float2 v0 = make_float2(acc[t][jj][0] + bv[jj].x, acc[t][jj][1] + bv[jj].y);
            float2 v1 = make_float2(acc[t][jj][2] + bv[jj].x, acc[t][jj][3] + bv[jj].y);
            *(float2*)(r0 + jj * 8) = v0;
            *(float2*)(r1 + jj * 8) = v1;
        }
    }
}

// ----------------------------------------------------------------------------
extern "C" void kernel_launch(void* const* d_in, const int* in_sizes, int n_in,
                              void* d_out, int out_size) {
    (void)in_sizes; (void)n_in; (void)out_size;
    const float* x = (const float*)d_in[0];
    const float* w = (const float*)d_in[1];
    const float* b = (const float*)d_in[2];
    float* out = (float*)d_out;

    cvt_x_kernel<<<2048, 256>>>(x);
    cvt_w_kernel<<<dim3(OUT_F / 32, IN_F / 32), dim3(32, 8)>>>(w);

    cudaFuncSetAttribute(gemm_hmma_kernel, cudaFuncAttributeMaxDynamicSharedMemorySize,
                         (int)SMEM_BYTES);
    gemm_hmma_kernel<<<(BATCH / TM) * (OUT_F / TN), 256, SMEM_BYTES>>>(b, out);
}

// round 3
// speedup vs baseline: 1.0472x; 1.0472x over previous
#include <cuda_runtime.h>
#include <cuda_fp16.h>
#include <cstdint>

// ============================================================================
// out[8192,4096] = x[8192,4096] @ W[4096(k),4096(n)] + b
// sm_103 base-ISA: cp.async multistage + ldmatrix + mma.sync.m16n8k16 (fp32 acc)
// R3: fragment double-buffering, single sync/iter, spread cp.async, fused cvt
// ============================================================================

static constexpr int BATCH = 8192;
static constexpr int IN_F  = 4096;   // K
static constexpr int OUT_F = 4096;   // N

static constexpr int TM = 128;
static constexpr int TN = 256;
static constexpr int KS = 64;              // K per stage
static constexpr int NK = IN_F / KS;       // 64
static constexpr int STAGES = 4;

static constexpr uint32_t A_ST = TM * 128u;                 // 16 KB
static constexpr uint32_t B_ST = TN * 128u;                 // 32 KB
static constexpr uint32_t STAGE = A_ST + B_ST;              // 48 KB
static constexpr uint32_t SMEM_BYTES = 1024u + STAGES * STAGE;

__device__ __align__(128) __half g_xh[(size_t)BATCH * IN_F];  // x fp16 [M,K]
__device__ __align__(128) __half g_wt[(size_t)OUT_F * IN_F];  // W^T fp16 [N,K]

// ----------------------------------------------------------------------------
__device__ __forceinline__ uint32_t smem_u32(const void* p) {
    uint32_t a;
    asm("{ .reg .u64 t; cvta.to.shared.u64 t, %1; cvt.u32.u64 %0, t; }" : "=r"(a) : "l"(p));
    return a;
}
__device__ __forceinline__ uint32_t sw128(uint32_t off) {
    return off ^ ((off >> 3) & 0x70u);
}
__device__ __forceinline__ void cp16(uint32_t s, const void* g) {
    asm volatile("cp.async.cg.shared.global [%0], [%1], 16;" :: "r"(s), "l"(g));
}
__device__ __forceinline__ void ldsm4(uint32_t& r0, uint32_t& r1, uint32_t& r2, uint32_t& r3,
                                      uint32_t addr) {
    asm volatile("ldmatrix.sync.aligned.m8n8.x4.shared.b16 {%0,%1,%2,%3}, [%4];"
                 : "=r"(r0), "=r"(r1), "=r"(r2), "=r"(r3) : "r"(addr));
}
__device__ __forceinline__ void mma16816(float& c0, float& c1, float& c2, float& c3,
                                         uint32_t a0, uint32_t a1, uint32_t a2, uint32_t a3,
                                         uint32_t b0, uint32_t b1) {
    asm volatile(
        "mma.sync.aligned.m16n8k16.row.col.f32.f16.f16.f32 "
        "{%0,%1,%2,%3}, {%4,%5,%6,%7}, {%8,%9}, {%0,%1,%2,%3};"
        : "+f"(c0), "+f"(c1), "+f"(c2), "+f"(c3)
        : "r"(a0), "r"(a1), "r"(a2), "r"(a3), "r"(b0), "r"(b1));
}

// ----------------------------------------------------------------------------
// Fused preprocessing: blocks [0, 16384) transpose+convert W; rest convert x.
// ----------------------------------------------------------------------------
static constexpr int W_BLOCKS = (OUT_F / 32) * (IN_F / 32);   // 16384
static constexpr int X_BLOCKS = 4096;

__global__ void __launch_bounds__(256)
cvt_fused_kernel(const float* __restrict__ x, const float* __restrict__ w) {
    const int bid = blockIdx.x;
    if (bid < W_BLOCKS) {
        __shared__ __half tile[32][33];
        const int bx = bid & ((OUT_F / 32) - 1);
        const int by = bid >> 7;                 // IN_F/32 = 128 -> 7 bits for bx
        const int i0 = by * 32;
        const int o0 = bx * 32;
        const int tx = threadIdx.x & 31;
        const int ty = threadIdx.x >> 5;         // 0..7
        #pragma unroll
        for (int k = 0; k < 4; k++) {
            int i = i0 + ty + k * 8;
            tile[ty + k * 8][tx] = __float2half(w[(size_t)i * OUT_F + o0 + tx]);
        }
        __syncthreads();
        #pragma unroll
        for (int k = 0; k < 4; k++) {
            int o = o0 + ty + k * 8;
            g_wt[(size_t)o * IN_F + i0 + tx] = tile[tx][ty + k * 8];
        }
    } else {
        const size_t n8 = (size_t)BATCH * IN_F / 8;
        const size_t stride = (size_t)X_BLOCKS * 256;
        for (size_t i = (size_t)(bid - W_BLOCKS) * 256 + threadIdx.x; i < n8; i += stride) {
            float4 a = ((const float4*)x)[2 * i];
            float4 c = ((const float4*)x)[2 * i + 1];
            __half2 h0 = __floats2half2_rn(a.x, a.y);
            __half2 h1 = __floats2half2_rn(a.z, a.w);
            __half2 h2 = __floats2half2_rn(c.x, c.y);
            __half2 h3 = __floats2half2_rn(c.z, c.w);
            uint4 o;
            o.x = *reinterpret_cast<uint32_t*>(&h0);
            o.y = *reinterpret_cast<uint32_t*>(&h1);
            o.z = *reinterpret_cast<uint32_t*>(&h2);
            o.w = *reinterpret_cast<uint32_t*>(&h3);
            ((uint4*)g_xh)[i] = o;
        }
    }
}

// ----------------------------------------------------------------------------
// GEMM: 128x256 tile / CTA, 256 threads (8 warps, 2M x 4N, warp tile 64x64)
// ----------------------------------------------------------------------------
__device__ __forceinline__ void load_chunk(uint32_t st, int tid,
                                           const __half* a, const __half* b, int q) {
    if (q < 4) {
        int id = tid + (q << 8);
        int row = id >> 3;
        int c = id & 7;
        uint32_t sw = sw128(((uint32_t)row << 7) | ((uint32_t)c << 4));
        cp16(st + sw, a + (size_t)row * IN_F + (c << 3));
    } else {
        int id = tid + ((q - 4) << 8);
        int row = id >> 3;
        int c = id & 7;
        uint32_t sw = sw128(((uint32_t)row << 7) | ((uint32_t)c << 4));
        cp16(st + A_ST + sw, b + (size_t)row * IN_F + (c << 3));
    }
}

__device__ __forceinline__ void load_stage(uint32_t st, int tid,
                                           const __half* gA, const __half* gB, int kslab) {
    const __half* a = gA + (size_t)kslab * KS;
    const __half* b = gB + (size_t)kslab * KS;
    #pragma unroll
    for (int q = 0; q < 12; q++) load_chunk(st, tid, a, b, q);
}

__global__ void __launch_bounds__(256, 1)
gemm_hmma_kernel(const float* __restrict__ bias, float* __restrict__ out) {
    extern __shared__ char smem_raw[];
    const uint32_t S0 = (smem_u32(smem_raw) + 1023u) & ~1023u;

    const int tid  = threadIdx.x;
    const int wid  = tid >> 5;
    const int lane = tid & 31;
    const int wm   = wid & 1;
    const int wn   = wid >> 1;
    const int tile_m = blockIdx.x >> 4;
    const int tile_n = blockIdx.x & 15;

    const __half* gA = g_xh + (size_t)tile_m * TM * IN_F;
    const __half* gB = g_wt + (size_t)tile_n * TN * IN_F;

    const uint32_t a_row  = (uint32_t)(wm * 64 + (lane & 15));
    const uint32_t a_colb = (uint32_t)((lane >> 4) << 4);
    const uint32_t b_row  = (uint32_t)(wn * 64 + ((lane >> 4) << 3) + (lane & 7));
    const uint32_t b_colb = (uint32_t)(((lane >> 3) & 1) << 4);

    float acc[4][8][4];
    #pragma unroll
    for (int t = 0; t < 4; t++)
        #pragma unroll
        for (int j = 0; j < 8; j++)
            #pragma unroll
            for (int q = 0; q < 4; q++) acc[t][j][q] = 0.0f;

    // Prologue: fill STAGES-1 stages
    #pragma unroll
    for (int p = 0; p < STAGES - 1; p++) {
        load_stage(S0 + (uint32_t)p * STAGE, tid, gA, gB, p);
        asm volatile("cp.async.commit_group;" ::: "memory");
    }

    uint32_t af[2][4][4], bf[2][4][4];

    for (int it = 0; it < NK; ++it) {
        asm volatile("cp.async.wait_group %0;" :: "n"(STAGES - 2) : "memory");
        __syncthreads();

        const uint32_t stA = S0 + (uint32_t)(it % STAGES) * STAGE;
        const uint32_t stB = stA + A_ST;

        const int j = it + (STAGES - 1);
        const bool doload = (j < NK);
        const uint32_t stN = S0 + (uint32_t)(j % STAGES) * STAGE;
        const __half* nA = gA + (size_t)j * KS;
        const __half* nB = gB + (size_t)j * KS;

        // preload kk=0 fragments
        #pragma unroll
        for (int t = 0; t < 4; t++) {
            uint32_t off = (a_row + t * 16u) * 128u + a_colb;
            ldsm4(af[0][t][0], af[0][t][1], af[0][t][2], af[0][t][3], stA + sw128(off));
        }
        #pragma unroll
        for (int p = 0; p < 4; p++) {
            uint32_t off = (b_row + p * 16u) * 128u + b_colb;
            ldsm4(bf[0][p][0], bf[0][p][1], bf[0][p][2], bf[0][p][3], stB + sw128(off));
        }

        #pragma unroll
        for (int kk = 0; kk < 4; kk++) {
            const int cur = kk & 1;
            const int nxt = cur ^ 1;
            // prefetch fragments for kk+1 (overlaps with MMAs below)
            if (kk < 3) {
                #pragma unroll
                for (int t = 0; t < 4; t++) {
                    uint32_t off = (a_row + t * 16u) * 128u + (uint32_t)((kk + 1) * 32) + a_colb;
                    ldsm4(af[nxt][t][0], af[nxt][t][1], af[nxt][t][2], af[nxt][t][3],
                          stA + sw128(off));
                }
                #pragma unroll
                for (int p = 0; p < 4; p++) {
                    uint32_t off = (b_row + p * 16u) * 128u + (uint32_t)((kk + 1) * 32) + b_colb;
                    ldsm4(bf[nxt][p][0], bf[nxt][p][1], bf[nxt][p][2], bf[nxt][p][3],
                          stB + sw128(off));
                }
            }
            // spread next-stage global loads: 3 chunks per kk
            if (doload) {
                #pragma unroll
                for (int c = 0; c < 3; c++) load_chunk(stN, tid, nA, nB, kk * 3 + c);
            }
            // 32 MMAs on current fragments
            #pragma unroll
            for (int t = 0; t < 4; t++) {
                #pragma unroll
                for (int p = 0; p < 4; p++) {
                    mma16816(acc[t][2*p][0], acc[t][2*p][1], acc[t][2*p][2], acc[t][2*p][3],
                             af[cur][t][0], af[cur][t][1], af[cur][t][2], af[cur][t][3],
                             bf[cur][p][0], bf[cur][p][1]);
                    mma16816(acc[t][2*p+1][0], acc[t][2*p+1][1], acc[t][2*p+1][2], acc[t][2*p+1][3],
                             af[cur][t][0], af[cur][t][1], af[cur][t][2], af[cur][t][3],
                             bf[cur][p][2], bf[cur][p][3]);
                }
            }
        }
        asm volatile("cp.async.commit_group;" ::: "memory");
        // no trailing __syncthreads: the next iteration's top barrier proves all
        // warps finished this iteration's ldmatrix reads before stage reuse.
    }

    // Epilogue: acc + bias -> gmem fp32
    const int n_base = tile_n * TN + wn * 64 + (lane & 3) * 2;
    float2 bv[8];
    #pragma unroll
    for (int jj = 0; jj < 8; jj++)
        bv[jj] = *(const float2*)(bias + n_base + jj * 8);

    const int m_base = tile_m * TM + wm * 64 + (lane >> 2);
    #pragma unroll
    for (int t = 0; t < 4; t++) {
        float* r0 = out + (size_t)(m_base + t * 16) * OUT_F + n_base;
        float* r1 = r0 + 8 * OUT_F;
        #pragma unroll
        for (int jj = 0; jj < 8; jj++) {
            float2 v0 = make_float2(acc[t][jj][0] + bv[jj].x, acc[t][jj][1] + bv[jj].y);
            float2 v1 = make_float2(acc[t][jj][2] + bv[jj].x, acc[t][jj][3] + bv[jj].y);
            *(float2*)(r0 + jj * 8) = v0;
            *(float2*)(r1 + jj * 8) = v1;
        }
    }
}

// ----------------------------------------------------------------------------
extern "C" void kernel_launch(void* const* d_in, const int* in_sizes, int n_in,
                              void* d_out, int out_size) {
    (void)in_sizes; (void)n_in; (void)out_size;
    const float* x = (const float*)d_in[0];
    const float* w = (const float*)d_in[1];
    const float* b = (const float*)d_in[2];
    float* out = (float*)d_out;

    cvt_fused_kernel<<<W_BLOCKS + X_BLOCKS, 256>>>(x, w);

    cudaFuncSetAttribute(gemm_hmma_kernel, cudaFuncAttributeMaxDynamicSharedMemorySize,
                         (int)SMEM_BYTES);
    gemm_hmma_kernel<<<(BATCH / TM) * (OUT_F / TN), 256, SMEM_BYTES>>>(b, out);
}